// round 13
// baseline (speedup 1.0000x reference)
#include <cuda_runtime.h>
#include <cuda_fp16.h>
#include <math.h>
#include <stddef.h>
#include <stdint.h>

// Problem constants
#define D_MODEL 768
#define NHEAD   12
#define HDIM    64
#define BATCH   8
#define TLEN    1024
#define SLEN    257
#define MROWS   (BATCH * TLEN)   // 8192
#define EROWS   (BATCH * SLEN)   // 2056
#define TPADC   320              // padded cross Vt length

// ---------------- scratch (static device globals; no allocation) ------------
__device__ __half g_big[(size_t)MROWS * 3072];
__device__ __half g_h  [(size_t)MROWS * D_MODEL];
__device__ __half g_o  [(size_t)MROWS * D_MODEL];
__device__ float  g_x  [(size_t)MROWS * D_MODEL];
__device__ __half g_q2 [(size_t)MROWS * D_MODEL];
__device__ __half g_ekv[(size_t)EROWS * 1536];
__device__ __half g_enc[(size_t)EROWS * D_MODEL];
__device__ __half g_vt [(size_t)BATCH * NHEAD * HDIM * TLEN];
__device__ __half g_vtc[(size_t)BATCH * NHEAD * HDIM * TPADC];
__device__ __half g_wt [9437184];   // converted+transposed weights

// WT offsets (halfs)
#define OFF_ATTN   0          // [2304][768]
#define OFF_APROJ  1769472    // [768][768]
#define OFF_CROSS  2359296    // [2304][768]
#define OFF_CPROJ  4128768    // [768][768]
#define OFF_FC     4718592    // [3072][768]
#define OFF_PROJ   7077888    // [768][3072]

// ------------------------------ helpers --------------------------------------
__device__ __forceinline__ float gelu_tanh(float v) {
    return 0.5f * v * (1.f + tanhf(0.7978845608028654f * (v + 0.044715f * v * v * v)));
}

__device__ __forceinline__ void mma_f16(float c[4],
    uint32_t a0, uint32_t a1, uint32_t a2, uint32_t a3,
    uint32_t b0, uint32_t b1)
{
    asm volatile(
        "mma.sync.aligned.m16n8k16.row.col.f32.f16.f16.f32 "
        "{%0,%1,%2,%3}, {%4,%5,%6,%7}, {%8,%9}, {%0,%1,%2,%3};"
        : "+f"(c[0]), "+f"(c[1]), "+f"(c[2]), "+f"(c[3])
        : "r"(a0), "r"(a1), "r"(a2), "r"(a3), "r"(b0), "r"(b1));
}

__device__ __forceinline__ void cp16(uint32_t dst_smem, const void* src) {
    asm volatile("cp.async.cg.shared.global [%0], [%1], 16;"
                 :: "r"(dst_smem), "l"(src));
}

__device__ __forceinline__ void ldsm_x4(
    uint32_t& r0, uint32_t& r1, uint32_t& r2, uint32_t& r3, uint32_t addr)
{
    asm volatile("ldmatrix.sync.aligned.m8n8.x4.shared.b16 {%0,%1,%2,%3}, [%4];"
                 : "=r"(r0), "=r"(r1), "=r"(r2), "=r"(r3) : "r"(addr));
}

__device__ __forceinline__ uint32_t pack_h2(float a, float b) {
    __half2 h = __floats2half2_rn(a, b);
    return *reinterpret_cast<uint32_t*>(&h);
}

// ---------------------------- LayerNorm (d = 768) ---------------------------
__global__ __launch_bounds__(256) void ln_kernel(
    const float* __restrict__ x, const float* __restrict__ g,
    const float* __restrict__ b, __half* __restrict__ y)
{
    const int row = blockIdx.x;
    const int tid = threadIdx.x;
    const float* xr = x + (size_t)row * D_MODEL;

    float v0 = xr[tid], v1 = xr[tid + 256], v2 = xr[tid + 512];
    float s  = v0 + v1 + v2;
    float sq = v0 * v0 + v1 * v1 + v2 * v2;

    #pragma unroll
    for (int off = 16; off >= 1; off >>= 1) {
        s  += __shfl_xor_sync(0xffffffffu, s,  off);
        sq += __shfl_xor_sync(0xffffffffu, sq, off);
    }
    __shared__ float ss[8], ssq[8];
    int w = tid >> 5, l = tid & 31;
    if (l == 0) { ss[w] = s; ssq[w] = sq; }
    __syncthreads();
    float st = 0.f, sqt = 0.f;
    #pragma unroll
    for (int i = 0; i < 8; i++) { st += ss[i]; sqt += ssq[i]; }

    const float mean = st * (1.f / 768.f);
    const float var  = sqt * (1.f / 768.f) - mean * mean;
    const float rstd = rsqrtf(var + 1e-5f);

    __half* yr = y + (size_t)row * D_MODEL;
    yr[tid]       = __float2half_rn((v0 - mean) * rstd * g[tid]       + b[tid]);
    yr[tid + 256] = __float2half_rn((v1 - mean) * rstd * g[tid + 256] + b[tid + 256]);
    yr[tid + 512] = __float2half_rn((v2 - mean) * rstd * g[tid + 512] + b[tid + 512]);
}

// ------------------- weight convert + transpose (fp32->fp16) -----------------
__global__ __launch_bounds__(256) void wconv_kernel(
    const float* __restrict__ src, __half* __restrict__ dst, int K, int N)
{
    __shared__ float t[32][33];
    const int k0 = blockIdx.y * 32, n0 = blockIdx.x * 32;
    const int tx = threadIdx.x & 31, ty = threadIdx.x >> 5;
    #pragma unroll
    for (int i = 0; i < 32; i += 8)
        t[ty + i][tx] = src[(size_t)(k0 + ty + i) * N + n0 + tx];
    __syncthreads();
    #pragma unroll
    for (int i = 0; i < 32; i += 8)
        dst[(size_t)(n0 + ty + i) * K + k0 + tx] = __float2half_rn(t[tx][ty + i]);
}

// -------------------------- encoder_x fp32 -> fp16 ---------------------------
__global__ __launch_bounds__(256) void f2h_kernel(
    const float* __restrict__ src, __half* __restrict__ dst, int n)
{
    int i = blockIdx.x * 256 + threadIdx.x;
    if (i < n) dst[i] = __float2half_rn(src[i]);
}

// ------------------------- V transpose (per b,h) ------------------------------
__global__ __launch_bounds__(256) void vtrans_kernel(
    const __half* __restrict__ src, __half* __restrict__ dst,
    int T, int src_rs, int dst_rs, int col_off)
{
    __shared__ __half tile[32][33];
    const int bh = blockIdx.z, b = bh / NHEAD, h = bh % NHEAD;
    const int t0 = blockIdx.x * 32, d0 = blockIdx.y * 32;
    const int tx = threadIdx.x & 31, ty = threadIdx.x >> 5;
    #pragma unroll
    for (int i = 0; i < 32; i += 8) {
        const int t = t0 + ty + i;
        __half v = __float2half(0.f);
        if (t < T) v = src[((size_t)b * T + t) * src_rs + col_off + h * HDIM + d0 + tx];
        tile[ty + i][tx] = v;
    }
    __syncthreads();
    #pragma unroll
    for (int i = 0; i < 32; i += 8)
        dst[((size_t)bh * HDIM + d0 + ty + i) * dst_rs + t0 + tx] = tile[tx][ty + i];
}

// ------------------------------ fp16 GEMM ------------------------------------
// C[M,N] = A[M,K] @ WT^T + bias (+resid | GELU). m16n8k16 fp16, fp32 acc.
// WT is [N][K] half. CTA 256x128xKT64, 512 thr (16 warps 4m x 4n), warp 64x32.
// One CTA/SM; B-tile traffic halved vs 128x128 (cp.async-issue bound fix).
#define GPITCH_B 144                       // bytes per row (36 u32)
#define GA_ROWS  256
#define GB_ROWS  128
#define GSTG_B   ((GA_ROWS + GB_ROWS) * GPITCH_B)   // 55296
#define GB_OFF   (GA_ROWS * GPITCH_B)                // 36864
#define GEMM_SMEM_BYTES (2 * GSTG_B)                 // 110592

__global__ __launch_bounds__(512, 1) void gemm_f16_kernel(
    const __half* __restrict__ A, int lda,
    const __half* __restrict__ WT, int ldb,
    const float* __restrict__ bias,
    const float* __restrict__ resid,
    void* __restrict__ Cv, int ldc,
    int M, int N, int K, int mode)   // 0: bias->half, 1: bias+resid->float, 2: bias+gelu->half
{
    extern __shared__ char smc[];
    const uint32_t smem0 = (uint32_t)__cvta_generic_to_shared(smc);
    const int tid = threadIdx.x, lane = tid & 31, wid = tid >> 5;
    const int wm = wid & 3, wn = wid >> 2;          // 4 (m) x 4 (n)
    const int g = lane >> 2, tg = lane & 3;
    const int bm = blockIdx.y * 256, bn = blockIdx.x * 128;

    // A loader: 512 thr, 2 per row (256 rows), 64B each (4 cp16)
    const int rowA = tid >> 1, hselA = tid & 1;
    int ar = bm + rowA; if (ar >= M) ar = M - 1;
    const __half* aptr = A + (size_t)ar * lda + hselA * 32;
    const uint32_t dA = smem0 + rowA * GPITCH_B + hselA * 64;

    // B loader: 4 per row (128 rows), 32B each (2 cp16)
    const int rowB = tid >> 2, qselB = tid & 3;
    const __half* bptr = WT + (size_t)(bn + rowB) * ldb + qselB * 16;
    const uint32_t dB = smem0 + GB_OFF + rowB * GPITCH_B + qselB * 32;

    // ldmatrix bases
    const uint32_t aLm = smem0 + (wm * 64 + (lane & 15)) * GPITCH_B + (lane >> 4) * 16;
    const uint32_t bLm = smem0 + GB_OFF
        + (wn * 32 + (lane & 7) + ((lane >> 4) << 3)) * GPITCH_B
        + ((lane >> 3) & 1) * 16;

    float acc[4][4][4];
    #pragma unroll
    for (int mt = 0; mt < 4; mt++)
        #pragma unroll
        for (int nt = 0; nt < 4; nt++)
            #pragma unroll
            for (int e = 0; e < 4; e++) acc[mt][nt][e] = 0.f;

    const int nk = K >> 6;   // K/64

    // prologue: stage 0
    #pragma unroll
    for (int j = 0; j < 4; j++) cp16(dA + j * 16, aptr + j * 8);
    cp16(dB, bptr);
    cp16(dB + 16, bptr + 8);
    asm volatile("cp.async.commit_group;");

    for (int kt = 0; kt < nk; kt++) {
        asm volatile("cp.async.wait_group 0;");
        __syncthreads();

        if (kt + 1 < nk) {
            const uint32_t so = ((kt + 1) & 1) * GSTG_B;
            const __half* pa = aptr + (size_t)(kt + 1) * 64;
            const __half* pb = bptr + (size_t)(kt + 1) * 64;
            #pragma unroll
            for (int j = 0; j < 4; j++) cp16(dA + so + j * 16, pa + j * 8);
            cp16(dB + so, pb);
            cp16(dB + so + 16, pb + 8);
            asm volatile("cp.async.commit_group;");
        }

        const uint32_t so = (kt & 1) * GSTG_B;

        #pragma unroll
        for (int ks = 0; ks < 4; ks++) {
            uint32_t af[4][4], bf[4][2];
            #pragma unroll
            for (int mt = 0; mt < 4; mt++)
                ldsm_x4(af[mt][0], af[mt][1], af[mt][2], af[mt][3],
                        aLm + so + mt * (16 * GPITCH_B) + ks * 32);
            #pragma unroll
            for (int p = 0; p < 2; p++) {
                uint32_t r0, r1, r2, r3;
                ldsm_x4(r0, r1, r2, r3, bLm + so + p * (16 * GPITCH_B) + ks * 32);
                bf[2 * p][0] = r0;     bf[2 * p][1] = r1;
                bf[2 * p + 1][0] = r2; bf[2 * p + 1][1] = r3;
            }
            #pragma unroll
            for (int mt = 0; mt < 4; mt++)
                #pragma unroll
                for (int nt = 0; nt < 4; nt++)
                    mma_f16(acc[mt][nt], af[mt][0], af[mt][1], af[mt][2], af[mt][3],
                            bf[nt][0], bf[nt][1]);
        }
    }

    // ---- epilogue ----
    #pragma unroll
    for (int mt = 0; mt < 4; mt++) {
        const int r0 = bm + wm * 64 + mt * 16 + g;
        #pragma unroll
        for (int h2 = 0; h2 < 2; h2++) {
            const int rr = r0 + 8 * h2;
            if (rr >= M) continue;
            #pragma unroll
            for (int nt = 0; nt < 4; nt++) {
                const int col = bn + wn * 32 + nt * 8 + 2 * tg;
                float ox = acc[mt][nt][2 * h2];
                float oy = acc[mt][nt][2 * h2 + 1];
                float2 bv = *(const float2*)&bias[col];
                ox += bv.x; oy += bv.y;
                if (mode == 1) {
                    float2 rv = *(const float2*)&resid[(size_t)rr * ldc + col];
                    ox += rv.x; oy += rv.y;
                    *(float2*)&((float*)Cv)[(size_t)rr * ldc + col] = make_float2(ox, oy);
                } else {
                    if (mode == 2) { ox = gelu_tanh(ox); oy = gelu_tanh(oy); }
                    __half2 hv = __floats2half2_rn(ox, oy);
                    *(__half2*)&((__half*)Cv)[(size_t)rr * ldc + col] = hv;
                }
            }
        }
    }
}

// ------------------- fp16 tensor-core flash attention -------------------------
// CTA: 128 q-rows x 64-key tiles, 256 thr = 8 warps; K/V double-buffered.
#define APITCH 144
#define AQ_OFF  0
#define AKSTG   (64 * APITCH)
#define AK_OFF  (128 * APITCH)
#define AV_OFF  (AK_OFF + 2 * AKSTG)
#define AP_OFF  (AV_OFF + 2 * AKSTG)
#define ATTN_SMEM_BYTES (AP_OFF + 128 * APITCH)     // 73728

__global__ __launch_bounds__(256, 2) void attn_f16_kernel(
    const __half* __restrict__ Qp, int q_rs,
    const __half* __restrict__ Kp, int k_rs,
    const __half* __restrict__ Vt, int vt_rs,
    __half* __restrict__ Op, int o_rs,
    int Tq, int Tk, int causal)
{
    extern __shared__ char smc[];
    const uint32_t smem0 = (uint32_t)__cvta_generic_to_shared(smc);
    uint32_t* P32 = (uint32_t*)(smc + AP_OFF);

    const int tid = threadIdx.x, lane = tid & 31, wid = tid >> 5;
    const int g = lane >> 2, tg = lane & 3;
    const int b = blockIdx.z, h = blockIdx.y;
    const int q0 = blockIdx.x * 128;
    const int rw = wid * 16;

    const __half* qbase = Qp + (size_t)b * Tq * q_rs + h * HDIM;
    const __half* kbase = Kp + (size_t)b * Tk * k_rs + h * HDIM;
    const __half* vbase = Vt + ((size_t)(b * NHEAD + h) * HDIM) * vt_rs;

    const uint32_t lmRow16 = (lane & 15) * APITCH + (lane >> 4) * 16;
    const uint32_t lmRowB  = ((lane & 7) + ((lane >> 4) << 3)) * APITCH
                           + ((lane >> 3) & 1) * 16;
    const uint32_t qLm = smem0 + AQ_OFF + rw * APITCH + lmRow16;
    const uint32_t kLm = smem0 + AK_OFF + lmRowB;
    const uint32_t vLm = smem0 + AV_OFF + lmRowB;
    const uint32_t pLm = smem0 + AP_OFF + rw * APITCH + lmRow16;

    const int kv_r = tid >> 2;
    const int kv_c = (tid & 3) * 16;
    const uint32_t dkBase = smem0 + AK_OFF + kv_r * APITCH + (tid & 3) * 32;
    const uint32_t dvBase = smem0 + AV_OFF + kv_r * APITCH + (tid & 3) * 32;

    const int ntiles = causal ? 2 * (blockIdx.x + 1) : ((Tk + 63) >> 6);

    {
        const int r = tid >> 1, hs = tid & 1;
        const __half* src = qbase + (size_t)(q0 + r) * q_rs + hs * 32;
        const uint32_t dst = smem0 + AQ_OFF + r * APITCH + hs * 64;
        #pragma unroll
        for (int j = 0; j < 4; j++) cp16(dst + j * 16, src + j * 8);
        asm volatile("cp.async.commit_group;");
    }
    {
        int sr = kv_r; if (sr >= Tk) sr = Tk - 1;
        const __half* ks = kbase + (size_t)sr * k_rs + kv_c;
        const __half* vs = vbase + (size_t)kv_r * vt_rs + kv_c;
        cp16(dkBase, ks);      cp16(dkBase + 16, ks + 8);
        cp16(dvBase, vs);      cp16(dvBase + 16, vs + 8);
        asm volatile("cp.async.commit_group;");
    }

    float mrun[2] = {-1e30f, -1e30f}, lrun[2] = {0.f, 0.f};
    float o[8][4];
    #pragma unroll
    for (int nf = 0; nf < 8; nf++)
        #pragma unroll
        for (int e = 0; e < 4; e++) o[nf][e] = 0.f;

    for (int kt = 0; kt < ntiles; kt++) {
        const int k0 = kt * 64;
        asm volatile("cp.async.wait_group 0;");
        __syncthreads();

        if (kt + 1 < ntiles) {
            const int k0n = k0 + 64;
            int sr = k0n + kv_r; if (sr >= Tk) sr = Tk - 1;
            const __half* ks = kbase + (size_t)sr * k_rs + kv_c;
            const __half* vs = vbase + (size_t)kv_r * vt_rs + k0n + kv_c;
            const uint32_t bo = ((kt + 1) & 1) * AKSTG;
            cp16(dkBase + bo, ks);      cp16(dkBase + bo + 16, ks + 8);
            cp16(dvBase + bo, vs);      cp16(dvBase + bo + 16, vs + 8);
            asm volatile("cp.async.commit_group;");
        }

        const uint32_t bo = (kt & 1) * AKSTG;

        float sc[8][4];
        #pragma unroll
        for (int nf = 0; nf < 8; nf++)
            #pragma unroll
            for (int e = 0; e < 4; e++) sc[nf][e] = 0.f;

        #pragma unroll
        for (int ks = 0; ks < 4; ks++) {
            uint32_t a0, a1, a2, a3;
            ldsm_x4(a0, a1, a2, a3, qLm + ks * 32);
            #pragma unroll
            for (int p = 0; p < 4; p++) {
                uint32_t b00, b01, b10, b11;
                ldsm_x4(b00, b01, b10, b11, kLm + bo + p * (16 * APITCH) + ks * 32);
                mma_f16(sc[2 * p],     a0, a1, a2, a3, b00, b01);
                mma_f16(sc[2 * p + 1], a0, a1, a2, a3, b10, b11);
            }
        }

        const int qi0 = q0 + rw + g, qi1 = qi0 + 8;
        const int cmax0 = causal ? min(qi0, Tk - 1) : (Tk - 1);
        const int cmax1 = causal ? min(qi1, Tk - 1) : (Tk - 1);
        float m0 = -1e30f, m1 = -1e30f;
        #pragma unroll
        for (int nf = 0; nf < 8; nf++) {
            const int c0i = k0 + 8 * nf + 2 * tg;
            const int c1i = c0i + 1;
            sc[nf][0] = (c0i <= cmax0) ? sc[nf][0] * 0.125f : -1e30f;
            sc[nf][1] = (c1i <= cmax0) ? sc[nf][1] * 0.125f : -1e30f;
            sc[nf][2] = (c0i <= cmax1) ? sc[nf][2] * 0.125f : -1e30f;
            sc[nf][3] = (c1i <= cmax1) ? sc[nf][3] * 0.125f : -1e30f;
            m0 = fmaxf(m0, fmaxf(sc[nf][0], sc[nf][1]));
            m1 = fmaxf(m1, fmaxf(sc[nf][2], sc[nf][3]));
        }
        #pragma unroll
        for (int off = 1; off < 4; off <<= 1) {
            m0 = fmaxf(m0, __shfl_xor_sync(0xffffffffu, m0, off));
            m1 = fmaxf(m1, __shfl_xor_sync(0xffffffffu, m1, off));
        }
        const float mn0 = fmaxf(mrun[0], m0), mn1 = fmaxf(mrun[1], m1);
        const float corr0 = __expf(mrun[0] - mn0), corr1 = __expf(mrun[1] - mn1);
        mrun[0] = mn0; mrun[1] = mn1;

        float s0 = 0.f, s1 = 0.f;
        #pragma unroll
        for (int nf = 0; nf < 8; nf++) {
            float p00 = __expf(sc[nf][0] - mn0);
            float p01 = __expf(sc[nf][1] - mn0);
            float p10 = __expf(sc[nf][2] - mn1);
            float p11 = __expf(sc[nf][3] - mn1);
            s0 += p00 + p01; s1 += p10 + p11;
            P32[(rw + g)     * 36 + 4 * nf + tg] = pack_h2(p00, p01);
            P32[(rw + g + 8) * 36 + 4 * nf + tg] = pack_h2(p10, p11);
            o[nf][0] *= corr0; o[nf][1] *= corr0;
            o[nf][2] *= corr1; o[nf][3] *= corr1;
        }
        #pragma unroll
        for (int off = 1; off < 4; off <<= 1) {
            s0 += __shfl_xor_sync(0xffffffffu, s0, off);
            s1 += __shfl_xor_sync(0xffffffffu, s1, off);
        }
        lrun[0] = lrun[0] * corr0 + s0;
        lrun[1] = lrun[1] * corr1 + s1;
        __syncwarp();

        #pragma unroll
        for (int ks = 0; ks < 4; ks++) {
            uint32_t a0, a1, a2, a3;
            ldsm_x4(a0, a1, a2, a3, pLm + ks * 32);
            #pragma unroll
            for (int p = 0; p < 4; p++) {
                uint32_t b00, b01, b10, b11;
                ldsm_x4(b00, b01, b10, b11, vLm + bo + p * (16 * APITCH) + ks * 32);
                mma_f16(o[2 * p],     a0, a1, a2, a3, b00, b01);
                mma_f16(o[2 * p + 1], a0, a1, a2, a3, b10, b11);
            }
        }
    }

    const float inv0 = 1.f / lrun[0], inv1 = 1.f / lrun[1];
    const int t0 = q0 + rw + g, t1 = t0 + 8;
    __half* out0 = Op + ((size_t)b * Tq + t0) * o_rs + h * HDIM;
    __half* out1 = Op + ((size_t)b * Tq + t1) * o_rs + h * HDIM;
    #pragma unroll
    for (int nf = 0; nf < 8; nf++) {
        const int col = 8 * nf + 2 * tg;
        *(__half2*)&out0[col] = __floats2half2_rn(o[nf][0] * inv0, o[nf][1] * inv0);
        *(__half2*)&out1[col] = __floats2half2_rn(o[nf][2] * inv1, o[nf][3] * inv1);
    }
}

// ------------------------------- launch --------------------------------------
extern "C" void kernel_launch(void* const* d_in, const int* in_sizes, int n_in,
                              void* d_out, int out_size)
{
    const float* x            = (const float*)d_in[0];
    const float* encoder_x    = (const float*)d_in[1];
    const float* ln1_g        = (const float*)d_in[2];
    const float* ln1_b        = (const float*)d_in[3];
    const float* ln2_g        = (const float*)d_in[4];
    const float* ln2_b        = (const float*)d_in[5];
    const float* ln3_g        = (const float*)d_in[6];
    const float* ln3_b        = (const float*)d_in[7];
    const float* attn_w       = (const float*)d_in[8];
    const float* attn_b       = (const float*)d_in[9];
    const float* attn_proj_w  = (const float*)d_in[10];
    const float* attn_proj_b  = (const float*)d_in[11];
    const float* cross_w      = (const float*)d_in[12];
    const float* cross_b      = (const float*)d_in[13];
    const float* cross_proj_w = (const float*)d_in[14];
    const float* cross_proj_b = (const float*)d_in[15];
    const float* fc_w         = (const float*)d_in[16];
    const float* fc_b         = (const float*)d_in[17];
    const float* proj_w       = (const float*)d_in[18];
    const float* proj_b       = (const float*)d_in[19];

    __half *big, *hbuf, *obuf, *q2, *ekv, *enc, *vt, *vtc, *wt;
    float  *xbuf;
    cudaGetSymbolAddress((void**)&big,  g_big);
    cudaGetSymbolAddress((void**)&hbuf, g_h);
    cudaGetSymbolAddress((void**)&obuf, g_o);
    cudaGetSymbolAddress((void**)&xbuf, g_x);
    cudaGetSymbolAddress((void**)&q2,   g_q2);
    cudaGetSymbolAddress((void**)&ekv,  g_ekv);
    cudaGetSymbolAddress((void**)&enc,  g_enc);
    cudaGetSymbolAddress((void**)&vt,   g_vt);
    cudaGetSymbolAddress((void**)&vtc,  g_vtc);
    cudaGetSymbolAddress((void**)&wt,   g_wt);

    cudaFuncSetAttribute(attn_f16_kernel,
                         cudaFuncAttributeMaxDynamicSharedMemorySize,
                         ATTN_SMEM_BYTES);
    cudaFuncSetAttribute(gemm_f16_kernel,
                         cudaFuncAttributeMaxDynamicSharedMemorySize,
                         GEMM_SMEM_BYTES);

    const int M = MROWS;        // 8192
    dim3 blk(256);
    dim3 gblk(512);
    dim3 ga(TLEN / 128, NHEAD, BATCH);   // 8 x 12 x 8
    const int MT = M / 256;              // 32
    const int ET = (EROWS + 255) / 256;  // 9

    // 0a. convert+transpose all weights (fp32 [K][N] -> fp16 [N][K])
    wconv_kernel<<<dim3(2304/32, 768/32),  blk>>>(attn_w,       wt + OFF_ATTN,  768, 2304);
    wconv_kernel<<<dim3(768/32,  768/32),  blk>>>(attn_proj_w,  wt + OFF_APROJ, 768, 768);
    wconv_kernel<<<dim3(2304/32, 768/32),  blk>>>(cross_w,      wt + OFF_CROSS, 768, 2304);
    wconv_kernel<<<dim3(768/32,  768/32),  blk>>>(cross_proj_w, wt + OFF_CPROJ, 768, 768);
    wconv_kernel<<<dim3(3072/32, 768/32),  blk>>>(fc_w,         wt + OFF_FC,    768, 3072);
    wconv_kernel<<<dim3(768/32,  3072/32), blk>>>(proj_w,       wt + OFF_PROJ,  3072, 768);
    // 0b. encoder_x -> half
    f2h_kernel<<<(EROWS * D_MODEL + 255) / 256, blk>>>(encoder_x, enc, EROWS * D_MODEL);

    // 1. h = LN1(x)
    ln_kernel<<<M, blk>>>(x, ln1_g, ln1_b, hbuf);
    // 2. qkv = h @ attn_w + attn_b  (8192 x 2304, half out)
    gemm_f16_kernel<<<dim3(2304/128, MT), gblk, GEMM_SMEM_BYTES>>>(
        hbuf, 768, wt + OFF_ATTN, 768, attn_b, nullptr, big, 2304, M, 2304, 768, 0);
    // 2b. transpose self V -> vt [bh][d][t]
    vtrans_kernel<<<dim3(TLEN/32, HDIM/32, BATCH*NHEAD), blk>>>(
        big, vt, TLEN, 2304, TLEN, 1536);
    // 3. causal self-attention
    attn_f16_kernel<<<ga, blk, ATTN_SMEM_BYTES>>>(
        big, 2304, big + 768, 2304, vt, TLEN, obuf, 768, TLEN, TLEN, 1);
    // 4. x1 = x + o @ attn_proj_w + attn_proj_b  (float out)
    gemm_f16_kernel<<<dim3(768/128, MT), gblk, GEMM_SMEM_BYTES>>>(
        obuf, 768, wt + OFF_APROJ, 768, attn_proj_b, x, xbuf, 768, M, 768, 768, 1);
    // 5. h = LN2(x1)
    ln_kernel<<<M, blk>>>(xbuf, ln2_g, ln2_b, hbuf);
    // 6. q2 = h @ cross_w[:, :768] + cross_b[:768]  (half out)
    gemm_f16_kernel<<<dim3(768/128, MT), gblk, GEMM_SMEM_BYTES>>>(
        hbuf, 768, wt + OFF_CROSS, 768, cross_b, nullptr, q2, 768, M, 768, 768, 0);
    // 7. ekv = encoder_x @ cross_w[:, 768:] + cross_b[768:]  (2056 x 1536, half)
    gemm_f16_kernel<<<dim3(1536/128, ET), gblk, GEMM_SMEM_BYTES>>>(
        enc, 768, wt + OFF_CROSS + 768 * 768, 768, cross_b + 768, nullptr,
        ekv, 1536, EROWS, 1536, 768, 0);
    // 7b. transpose cross V -> vtc [bh][d][t_pad] (zero-padded to 320)
    vtrans_kernel<<<dim3(TPADC/32, HDIM/32, BATCH*NHEAD), blk>>>(
        ekv, vtc, SLEN, 1536, TPADC, 768);
    // 8. cross-attention (non-causal, Tk = 257)
    attn_f16_kernel<<<ga, blk, ATTN_SMEM_BYTES>>>(
        q2, 768, ekv, 1536, vtc, TPADC, obuf, 768, TLEN, SLEN, 0);
    // 9. x2 = x1 + o2 @ cross_proj_w + cross_proj_b  (float out, in-place resid)
    gemm_f16_kernel<<<dim3(768/128, MT), gblk, GEMM_SMEM_BYTES>>>(
        obuf, 768, wt + OFF_CPROJ, 768, cross_proj_b, xbuf, xbuf, 768, M, 768, 768, 1);
    // 10. h = LN3(x2)
    ln_kernel<<<M, blk>>>(xbuf, ln3_g, ln3_b, hbuf);
    // 11. fc = GELU(h @ fc_w + fc_b)  (8192 x 3072, half out)
    gemm_f16_kernel<<<dim3(3072/128, MT), gblk, GEMM_SMEM_BYTES>>>(
        hbuf, 768, wt + OFF_FC, 768, fc_b, nullptr, big, 3072, M, 3072, 768, 2);
    // 12. out = x2 + fc @ proj_w + proj_b  (float out)
    gemm_f16_kernel<<<dim3(768/128, MT), gblk, GEMM_SMEM_BYTES>>>(
        big, 3072, wt + OFF_PROJ, 3072, proj_b, xbuf, (float*)d_out, 768, M, 768, 3072, 1);
}

// round 14
// speedup vs baseline: 1.1281x; 1.1281x over previous
#include <cuda_runtime.h>
#include <cuda_fp16.h>
#include <math.h>
#include <stddef.h>
#include <stdint.h>

// Problem constants
#define D_MODEL 768
#define NHEAD   12
#define HDIM    64
#define BATCH   8
#define TLEN    1024
#define SLEN    257
#define MROWS   (BATCH * TLEN)   // 8192
#define EROWS   (BATCH * SLEN)   // 2056

// ---------------- scratch (static device globals; no allocation) ------------
__device__ __half g_big[(size_t)MROWS * 3072];
__device__ __half g_h  [(size_t)MROWS * D_MODEL];
__device__ __half g_o  [(size_t)MROWS * D_MODEL];
__device__ float  g_x  [(size_t)MROWS * D_MODEL];
__device__ __half g_q2 [(size_t)MROWS * D_MODEL];
__device__ __half g_ekv[(size_t)EROWS * 1536];
__device__ __half g_enc[(size_t)EROWS * D_MODEL];
__device__ __half g_wt [9437184];   // converted+transposed weights

// WT offsets (halfs)
#define OFF_ATTN   0          // [2304][768]
#define OFF_APROJ  1769472    // [768][768]
#define OFF_CROSS  2359296    // [2304][768]
#define OFF_CPROJ  4128768    // [768][768]
#define OFF_FC     4718592    // [3072][768]
#define OFF_PROJ   7077888    // [768][3072]

// ------------------------------ helpers --------------------------------------
__device__ __forceinline__ float gelu_tanh(float v) {
    return 0.5f * v * (1.f + tanhf(0.7978845608028654f * (v + 0.044715f * v * v * v)));
}

__device__ __forceinline__ void mma_f16(float c[4],
    uint32_t a0, uint32_t a1, uint32_t a2, uint32_t a3,
    uint32_t b0, uint32_t b1)
{
    asm volatile(
        "mma.sync.aligned.m16n8k16.row.col.f32.f16.f16.f32 "
        "{%0,%1,%2,%3}, {%4,%5,%6,%7}, {%8,%9}, {%0,%1,%2,%3};"
        : "+f"(c[0]), "+f"(c[1]), "+f"(c[2]), "+f"(c[3])
        : "r"(a0), "r"(a1), "r"(a2), "r"(a3), "r"(b0), "r"(b1));
}

__device__ __forceinline__ void cp16(uint32_t dst_smem, const void* src) {
    asm volatile("cp.async.cg.shared.global [%0], [%1], 16;"
                 :: "r"(dst_smem), "l"(src));
}

__device__ __forceinline__ void ldsm_x4(
    uint32_t& r0, uint32_t& r1, uint32_t& r2, uint32_t& r3, uint32_t addr)
{
    asm volatile("ldmatrix.sync.aligned.m8n8.x4.shared.b16 {%0,%1,%2,%3}, [%4];"
                 : "=r"(r0), "=r"(r1), "=r"(r2), "=r"(r3) : "r"(addr));
}

__device__ __forceinline__ void ldsm_x4_t(
    uint32_t& r0, uint32_t& r1, uint32_t& r2, uint32_t& r3, uint32_t addr)
{
    asm volatile("ldmatrix.sync.aligned.m8n8.x4.trans.shared.b16 {%0,%1,%2,%3}, [%4];"
                 : "=r"(r0), "=r"(r1), "=r"(r2), "=r"(r3) : "r"(addr));
}

__device__ __forceinline__ uint32_t pack_h2(float a, float b) {
    __half2 h = __floats2half2_rn(a, b);
    return *reinterpret_cast<uint32_t*>(&h);
}

// ---------------------------- LayerNorm (d = 768) ---------------------------
__global__ __launch_bounds__(256) void ln_kernel(
    const float* __restrict__ x, const float* __restrict__ g,
    const float* __restrict__ b, __half* __restrict__ y)
{
    const int row = blockIdx.x;
    const int tid = threadIdx.x;
    const float* xr = x + (size_t)row * D_MODEL;

    float v0 = xr[tid], v1 = xr[tid + 256], v2 = xr[tid + 512];
    float s  = v0 + v1 + v2;
    float sq = v0 * v0 + v1 * v1 + v2 * v2;

    #pragma unroll
    for (int off = 16; off >= 1; off >>= 1) {
        s  += __shfl_xor_sync(0xffffffffu, s,  off);
        sq += __shfl_xor_sync(0xffffffffu, sq, off);
    }
    __shared__ float ss[8], ssq[8];
    int w = tid >> 5, l = tid & 31;
    if (l == 0) { ss[w] = s; ssq[w] = sq; }
    __syncthreads();
    float st = 0.f, sqt = 0.f;
    #pragma unroll
    for (int i = 0; i < 8; i++) { st += ss[i]; sqt += ssq[i]; }

    const float mean = st * (1.f / 768.f);
    const float var  = sqt * (1.f / 768.f) - mean * mean;
    const float rstd = rsqrtf(var + 1e-5f);

    __half* yr = y + (size_t)row * D_MODEL;
    yr[tid]       = __float2half_rn((v0 - mean) * rstd * g[tid]       + b[tid]);
    yr[tid + 256] = __float2half_rn((v1 - mean) * rstd * g[tid + 256] + b[tid + 256]);
    yr[tid + 512] = __float2half_rn((v2 - mean) * rstd * g[tid + 512] + b[tid + 512]);
}

// ------------------- weight convert + transpose (fp32->fp16) -----------------
__global__ __launch_bounds__(256) void wconv_kernel(
    const float* __restrict__ src, __half* __restrict__ dst, int K, int N)
{
    __shared__ float t[32][33];
    const int k0 = blockIdx.y * 32, n0 = blockIdx.x * 32;
    const int tx = threadIdx.x & 31, ty = threadIdx.x >> 5;
    #pragma unroll
    for (int i = 0; i < 32; i += 8)
        t[ty + i][tx] = src[(size_t)(k0 + ty + i) * N + n0 + tx];
    __syncthreads();
    #pragma unroll
    for (int i = 0; i < 32; i += 8)
        dst[(size_t)(n0 + ty + i) * K + k0 + tx] = __float2half_rn(t[tx][ty + i]);
}

// -------------------------- encoder_x fp32 -> fp16 ---------------------------
__global__ __launch_bounds__(256) void f2h_kernel(
    const float* __restrict__ src, __half* __restrict__ dst, int n)
{
    int i = blockIdx.x * 256 + threadIdx.x;
    if (i < n) dst[i] = __float2half_rn(src[i]);
}

// ------------------------------ fp16 GEMM ------------------------------------
// C[M,N] = A[M,K] @ WT^T + bias (+resid | GELU). m16n8k16 fp16, fp32 acc.
// WT is [N][K] half. CTA 128x128xKT64, 256 thr (8 warps 2m x 4n), warp 64x32.
// Fragments via ldmatrix.x4 (pitch 144B -> conflict-free). (R12 config)
#define GPITCH_B 144                     // bytes per row (36 u32)
#define GSTG_B   (256 * GPITCH_B)        // 36864
#define GEMM_SMEM_BYTES (2 * GSTG_B)     // 73728

__global__ __launch_bounds__(256, 2) void gemm_f16_kernel(
    const __half* __restrict__ A, int lda,
    const __half* __restrict__ WT, int ldb,
    const float* __restrict__ bias,
    const float* __restrict__ resid,
    void* __restrict__ Cv, int ldc,
    int M, int N, int K, int mode)   // 0: bias->half, 1: bias+resid->float, 2: bias+gelu->half
{
    extern __shared__ char smc[];
    const uint32_t smem0 = (uint32_t)__cvta_generic_to_shared(smc);
    const int tid = threadIdx.x, lane = tid & 31, wid = tid >> 5;
    const int wm = wid & 1, wn = wid >> 1;
    const int g = lane >> 2, tg = lane & 3;
    const int bm = blockIdx.y * 128, bn = blockIdx.x * 128;

    const int row = tid >> 1, hsel = tid & 1;
    int ar = bm + row; if (ar >= M) ar = M - 1;
    const __half* aptr = A  + (size_t)ar * lda + hsel * 32;
    const __half* bptr = WT + (size_t)(bn + row) * ldb + hsel * 32;
    const uint32_t dA = smem0 + row * GPITCH_B + hsel * 64;
    const uint32_t dB = smem0 + 128 * GPITCH_B + row * GPITCH_B + hsel * 64;

    const uint32_t aLm = smem0 + (wm * 64 + (lane & 15)) * GPITCH_B + (lane >> 4) * 16;
    const uint32_t bLm = smem0 + 128 * GPITCH_B
        + (wn * 32 + (lane & 7) + ((lane >> 4) << 3)) * GPITCH_B
        + ((lane >> 3) & 1) * 16;

    float acc[4][4][4];
    #pragma unroll
    for (int mt = 0; mt < 4; mt++)
        #pragma unroll
        for (int nt = 0; nt < 4; nt++)
            #pragma unroll
            for (int e = 0; e < 4; e++) acc[mt][nt][e] = 0.f;

    const int nk = K >> 6;   // K/64

    #pragma unroll
    for (int j = 0; j < 4; j++) {
        cp16(dA + j * 16, aptr + j * 8);
        cp16(dB + j * 16, bptr + j * 8);
    }
    asm volatile("cp.async.commit_group;");

    for (int kt = 0; kt < nk; kt++) {
        asm volatile("cp.async.wait_group 0;");
        __syncthreads();

        if (kt + 1 < nk) {
            const int st = (kt + 1) & 1;
            const __half* pa = aptr + (size_t)(kt + 1) * 64;
            const __half* pb = bptr + (size_t)(kt + 1) * 64;
            const uint32_t oA = dA + st * GSTG_B;
            const uint32_t oB = dB + st * GSTG_B;
            #pragma unroll
            for (int j = 0; j < 4; j++) {
                cp16(oA + j * 16, pa + j * 8);
                cp16(oB + j * 16, pb + j * 8);
            }
            asm volatile("cp.async.commit_group;");
        }

        const uint32_t so = (kt & 1) * GSTG_B;

        #pragma unroll
        for (int ks = 0; ks < 4; ks++) {
            uint32_t af[4][4], bf[4][2];
            #pragma unroll
            for (int mt = 0; mt < 4; mt++)
                ldsm_x4(af[mt][0], af[mt][1], af[mt][2], af[mt][3],
                        aLm + so + mt * (16 * GPITCH_B) + ks * 32);
            #pragma unroll
            for (int p = 0; p < 2; p++) {
                uint32_t r0, r1, r2, r3;
                ldsm_x4(r0, r1, r2, r3, bLm + so + p * (16 * GPITCH_B) + ks * 32);
                bf[2 * p][0] = r0;     bf[2 * p][1] = r1;
                bf[2 * p + 1][0] = r2; bf[2 * p + 1][1] = r3;
            }
            #pragma unroll
            for (int mt = 0; mt < 4; mt++)
                #pragma unroll
                for (int nt = 0; nt < 4; nt++)
                    mma_f16(acc[mt][nt], af[mt][0], af[mt][1], af[mt][2], af[mt][3],
                            bf[nt][0], bf[nt][1]);
        }
    }

    // ---- epilogue ----
    #pragma unroll
    for (int mt = 0; mt < 4; mt++) {
        const int r0 = bm + wm * 64 + mt * 16 + g;
        #pragma unroll
        for (int h2 = 0; h2 < 2; h2++) {
            const int rr = r0 + 8 * h2;
            if (rr >= M) continue;
            #pragma unroll
            for (int nt = 0; nt < 4; nt++) {
                const int col = bn + wn * 32 + nt * 8 + 2 * tg;
                float ox = acc[mt][nt][2 * h2];
                float oy = acc[mt][nt][2 * h2 + 1];
                float2 bv = *(const float2*)&bias[col];
                ox += bv.x; oy += bv.y;
                if (mode == 1) {
                    float2 rv = *(const float2*)&resid[(size_t)rr * ldc + col];
                    ox += rv.x; oy += rv.y;
                    *(float2*)&((float*)Cv)[(size_t)rr * ldc + col] = make_float2(ox, oy);
                } else {
                    if (mode == 2) { ox = gelu_tanh(ox); oy = gelu_tanh(oy); }
                    __half2 hv = __floats2half2_rn(ox, oy);
                    *(__half2*)&((__half*)Cv)[(size_t)rr * ldc + col] = hv;
                }
            }
        }
    }
}

// ------------------- fp16 tensor-core flash attention -------------------------
// CTA: 128 q-rows x 64-key tiles, 256 thr = 8 warps; K/V double-buffered.
// V consumed in NATURAL [t][d] layout via ldmatrix.trans (no pre-transpose).
#define APITCH 144
#define AQ_OFF  0
#define AKSTG   (64 * APITCH)
#define AK_OFF  (128 * APITCH)
#define AV_OFF  (AK_OFF + 2 * AKSTG)
#define AP_OFF  (AV_OFF + 2 * AKSTG)
#define ATTN_SMEM_BYTES (AP_OFF + 128 * APITCH)     // 73728

__global__ __launch_bounds__(256, 2) void attn_f16_kernel(
    const __half* __restrict__ Qp, int q_rs,
    const __half* __restrict__ Kp, int k_rs,
    const __half* __restrict__ Vp, int v_rs,    // natural [t][d] rows
    __half* __restrict__ Op, int o_rs,
    int Tq, int Tk, int causal)
{
    extern __shared__ char smc[];
    const uint32_t smem0 = (uint32_t)__cvta_generic_to_shared(smc);
    uint32_t* P32 = (uint32_t*)(smc + AP_OFF);

    const int tid = threadIdx.x, lane = tid & 31, wid = tid >> 5;
    const int g = lane >> 2, tg = lane & 3;
    const int b = blockIdx.z, h = blockIdx.y;
    const int q0 = blockIdx.x * 128;
    const int rw = wid * 16;

    const __half* qbase = Qp + (size_t)b * Tq * q_rs + h * HDIM;
    const __half* kbase = Kp + (size_t)b * Tk * k_rs + h * HDIM;
    const __half* vbase = Vp + (size_t)b * Tk * v_rs + h * HDIM;

    // ldmatrix bases
    const uint32_t lmRow16 = (lane & 15) * APITCH + (lane >> 4) * 16;   // A-style
    const uint32_t lmRowB  = ((lane & 7) + ((lane >> 4) << 3)) * APITCH
                           + ((lane >> 3) & 1) * 16;                    // B-style (K)
    const uint32_t lmRowVT = ((lane & 7) + ((lane >> 3) & 1) * 8) * APITCH
                           + (lane >> 4) * 16;                          // B-trans (V)
    const uint32_t qLm = smem0 + AQ_OFF + rw * APITCH + lmRow16;
    const uint32_t kLm = smem0 + AK_OFF + lmRowB;
    const uint32_t vLm = smem0 + AV_OFF + lmRowVT;
    const uint32_t pLm = smem0 + AP_OFF + rw * APITCH + lmRow16;

    // K/V loader mapping (identical: rows = t, cols = d)
    const int kv_r = tid >> 2;
    const int kv_c = (tid & 3) * 16;
    const uint32_t dkBase = smem0 + AK_OFF + kv_r * APITCH + (tid & 3) * 32;
    const uint32_t dvBase = smem0 + AV_OFF + kv_r * APITCH + (tid & 3) * 32;

    const int ntiles = causal ? 2 * (blockIdx.x + 1) : ((Tk + 63) >> 6);

    // prologue: Q load + K/V tile 0
    {
        const int r = tid >> 1, hs = tid & 1;
        const __half* src = qbase + (size_t)(q0 + r) * q_rs + hs * 32;
        const uint32_t dst = smem0 + AQ_OFF + r * APITCH + hs * 64;
        #pragma unroll
        for (int j = 0; j < 4; j++) cp16(dst + j * 16, src + j * 8);
        asm volatile("cp.async.commit_group;");
    }
    {
        int sr = kv_r; if (sr >= Tk) sr = Tk - 1;
        const __half* ks = kbase + (size_t)sr * k_rs + kv_c;
        const __half* vs = vbase + (size_t)sr * v_rs + kv_c;
        cp16(dkBase, ks);      cp16(dkBase + 16, ks + 8);
        cp16(dvBase, vs);      cp16(dvBase + 16, vs + 8);
        asm volatile("cp.async.commit_group;");
    }

    float mrun[2] = {-1e30f, -1e30f}, lrun[2] = {0.f, 0.f};
    float o[8][4];
    #pragma unroll
    for (int nf = 0; nf < 8; nf++)
        #pragma unroll
        for (int e = 0; e < 4; e++) o[nf][e] = 0.f;

    for (int kt = 0; kt < ntiles; kt++) {
        const int k0 = kt * 64;
        asm volatile("cp.async.wait_group 0;");
        __syncthreads();

        // prefetch tile kt+1 into buffer (kt+1)&1
        if (kt + 1 < ntiles) {
            const int k0n = k0 + 64;
            int sr = k0n + kv_r; if (sr >= Tk) sr = Tk - 1;
            const __half* ks = kbase + (size_t)sr * k_rs + kv_c;
            const __half* vs = vbase + (size_t)sr * v_rs + kv_c;
            const uint32_t bo = ((kt + 1) & 1) * AKSTG;
            cp16(dkBase + bo, ks);      cp16(dkBase + bo + 16, ks + 8);
            cp16(dvBase + bo, vs);      cp16(dvBase + bo + 16, vs + 8);
            asm volatile("cp.async.commit_group;");
        }

        const uint32_t bo = (kt & 1) * AKSTG;

        // ---- S = Q K^T ----
        float sc[8][4];
        #pragma unroll
        for (int nf = 0; nf < 8; nf++)
            #pragma unroll
            for (int e = 0; e < 4; e++) sc[nf][e] = 0.f;

        #pragma unroll
        for (int ks = 0; ks < 4; ks++) {
            uint32_t a0, a1, a2, a3;
            ldsm_x4(a0, a1, a2, a3, qLm + ks * 32);
            #pragma unroll
            for (int p = 0; p < 4; p++) {
                uint32_t b00, b01, b10, b11;
                ldsm_x4(b00, b01, b10, b11, kLm + bo + p * (16 * APITCH) + ks * 32);
                mma_f16(sc[2 * p],     a0, a1, a2, a3, b00, b01);
                mma_f16(sc[2 * p + 1], a0, a1, a2, a3, b10, b11);
            }
        }

        // ---- scale + mask + online softmax ----
        const int qi0 = q0 + rw + g, qi1 = qi0 + 8;
        const int cmax0 = causal ? min(qi0, Tk - 1) : (Tk - 1);
        const int cmax1 = causal ? min(qi1, Tk - 1) : (Tk - 1);
        float m0 = -1e30f, m1 = -1e30f;
        #pragma unroll
        for (int nf = 0; nf < 8; nf++) {
            const int c0i = k0 + 8 * nf + 2 * tg;
            const int c1i = c0i + 1;
            sc[nf][0] = (c0i <= cmax0) ? sc[nf][0] * 0.125f : -1e30f;
            sc[nf][1] = (c1i <= cmax0) ? sc[nf][1] * 0.125f : -1e30f;
            sc[nf][2] = (c0i <= cmax1) ? sc[nf][2] * 0.125f : -1e30f;
            sc[nf][3] = (c1i <= cmax1) ? sc[nf][3] * 0.125f : -1e30f;
            m0 = fmaxf(m0, fmaxf(sc[nf][0], sc[nf][1]));
            m1 = fmaxf(m1, fmaxf(sc[nf][2], sc[nf][3]));
        }
        #pragma unroll
        for (int off = 1; off < 4; off <<= 1) {
            m0 = fmaxf(m0, __shfl_xor_sync(0xffffffffu, m0, off));
            m1 = fmaxf(m1, __shfl_xor_sync(0xffffffffu, m1, off));
        }
        const float mn0 = fmaxf(mrun[0], m0), mn1 = fmaxf(mrun[1], m1);
        const float corr0 = __expf(mrun[0] - mn0), corr1 = __expf(mrun[1] - mn1);
        mrun[0] = mn0; mrun[1] = mn1;

        float s0 = 0.f, s1 = 0.f;
        #pragma unroll
        for (int nf = 0; nf < 8; nf++) {
            float p00 = __expf(sc[nf][0] - mn0);
            float p01 = __expf(sc[nf][1] - mn0);
            float p10 = __expf(sc[nf][2] - mn1);
            float p11 = __expf(sc[nf][3] - mn1);
            s0 += p00 + p01; s1 += p10 + p11;
            P32[(rw + g)     * 36 + 4 * nf + tg] = pack_h2(p00, p01);
            P32[(rw + g + 8) * 36 + 4 * nf + tg] = pack_h2(p10, p11);
            o[nf][0] *= corr0; o[nf][1] *= corr0;
            o[nf][2] *= corr1; o[nf][3] *= corr1;
        }
        #pragma unroll
        for (int off = 1; off < 4; off <<= 1) {
            s0 += __shfl_xor_sync(0xffffffffu, s0, off);
            s1 += __shfl_xor_sync(0xffffffffu, s1, off);
        }
        lrun[0] = lrun[0] * corr0 + s0;
        lrun[1] = lrun[1] * corr1 + s1;
        __syncwarp();

        // ---- O += P V (V natural layout, trans ldmatrix) ----
        #pragma unroll
        for (int ks = 0; ks < 4; ks++) {
            uint32_t a0, a1, a2, a3;
            ldsm_x4(a0, a1, a2, a3, pLm + ks * 32);
            #pragma unroll
            for (int p = 0; p < 4; p++) {
                uint32_t b00, b01, b10, b11;
                ldsm_x4_t(b00, b01, b10, b11,
                          vLm + bo + ks * (16 * APITCH) + p * 32);
                mma_f16(o[2 * p],     a0, a1, a2, a3, b00, b01);
                mma_f16(o[2 * p + 1], a0, a1, a2, a3, b10, b11);
            }
        }
    }

    const float inv0 = 1.f / lrun[0], inv1 = 1.f / lrun[1];
    const int t0 = q0 + rw + g, t1 = t0 + 8;
    __half* out0 = Op + ((size_t)b * Tq + t0) * o_rs + h * HDIM;
    __half* out1 = Op + ((size_t)b * Tq + t1) * o_rs + h * HDIM;
    #pragma unroll
    for (int nf = 0; nf < 8; nf++) {
        const int col = 8 * nf + 2 * tg;
        *(__half2*)&out0[col] = __floats2half2_rn(o[nf][0] * inv0, o[nf][1] * inv0);
        *(__half2*)&out1[col] = __floats2half2_rn(o[nf][2] * inv1, o[nf][3] * inv1);
    }
}

// ------------------------------- launch --------------------------------------
extern "C" void kernel_launch(void* const* d_in, const int* in_sizes, int n_in,
                              void* d_out, int out_size)
{
    const float* x            = (const float*)d_in[0];
    const float* encoder_x    = (const float*)d_in[1];
    const float* ln1_g        = (const float*)d_in[2];
    const float* ln1_b        = (const float*)d_in[3];
    const float* ln2_g        = (const float*)d_in[4];
    const float* ln2_b        = (const float*)d_in[5];
    const float* ln3_g        = (const float*)d_in[6];
    const float* ln3_b        = (const float*)d_in[7];
    const float* attn_w       = (const float*)d_in[8];
    const float* attn_b       = (const float*)d_in[9];
    const float* attn_proj_w  = (const float*)d_in[10];
    const float* attn_proj_b  = (const float*)d_in[11];
    const float* cross_w      = (const float*)d_in[12];
    const float* cross_b      = (const float*)d_in[13];
    const float* cross_proj_w = (const float*)d_in[14];
    const float* cross_proj_b = (const float*)d_in[15];
    const float* fc_w         = (const float*)d_in[16];
    const float* fc_b         = (const float*)d_in[17];
    const float* proj_w       = (const float*)d_in[18];
    const float* proj_b       = (const float*)d_in[19];

    __half *big, *hbuf, *obuf, *q2, *ekv, *enc, *wt;
    float  *xbuf;
    cudaGetSymbolAddress((void**)&big,  g_big);
    cudaGetSymbolAddress((void**)&hbuf, g_h);
    cudaGetSymbolAddress((void**)&obuf, g_o);
    cudaGetSymbolAddress((void**)&xbuf, g_x);
    cudaGetSymbolAddress((void**)&q2,   g_q2);
    cudaGetSymbolAddress((void**)&ekv,  g_ekv);
    cudaGetSymbolAddress((void**)&enc,  g_enc);
    cudaGetSymbolAddress((void**)&wt,   g_wt);

    cudaFuncSetAttribute(attn_f16_kernel,
                         cudaFuncAttributeMaxDynamicSharedMemorySize,
                         ATTN_SMEM_BYTES);
    cudaFuncSetAttribute(gemm_f16_kernel,
                         cudaFuncAttributeMaxDynamicSharedMemorySize,
                         GEMM_SMEM_BYTES);

    const int M = MROWS;        // 8192
    dim3 blk(256);
    dim3 ga(TLEN / 128, NHEAD, BATCH);   // 8 x 12 x 8

    // Launch order arranged so launch #6 (ncu -s 5 -c 1) is the qkv GEMM.
    // 1. wconv attn
    wconv_kernel<<<dim3(2304/32, 768/32),  blk>>>(attn_w,       wt + OFF_ATTN,  768, 2304);
    // 2. wconv attn_proj
    wconv_kernel<<<dim3(768/32,  768/32),  blk>>>(attn_proj_w,  wt + OFF_APROJ, 768, 768);
    // 3. encoder_x -> half
    f2h_kernel<<<(EROWS * D_MODEL + 255) / 256, blk>>>(encoder_x, enc, EROWS * D_MODEL);
    // 4. h = LN1(x)
    ln_kernel<<<M, blk>>>(x, ln1_g, ln1_b, hbuf);
    // 5. wconv cross
    wconv_kernel<<<dim3(2304/32, 768/32),  blk>>>(cross_w,      wt + OFF_CROSS, 768, 2304);
    // 6. qkv = h @ attn_w + attn_b  (8192 x 2304, half out)  <-- PROFILED
    gemm_f16_kernel<<<dim3(2304/128, M/128), blk, GEMM_SMEM_BYTES>>>(
        hbuf, 768, wt + OFF_ATTN, 768, attn_b, nullptr, big, 2304, M, 2304, 768, 0);
    // 7. causal self-attention (V natural from qkv)
    attn_f16_kernel<<<ga, blk, ATTN_SMEM_BYTES>>>(
        big, 2304, big + 768, 2304, big + 1536, 2304, obuf, 768, TLEN, TLEN, 1);
    // 8. x1 = x + o @ attn_proj_w + attn_proj_b  (float out)
    gemm_f16_kernel<<<dim3(768/128, M/128), blk, GEMM_SMEM_BYTES>>>(
        obuf, 768, wt + OFF_APROJ, 768, attn_proj_b, x, xbuf, 768, M, 768, 768, 1);
    // 9. h = LN2(x1)
    ln_kernel<<<M, blk>>>(xbuf, ln2_g, ln2_b, hbuf);
    // 10. wconv cross_proj
    wconv_kernel<<<dim3(768/32,  768/32),  blk>>>(cross_proj_w, wt + OFF_CPROJ, 768, 768);
    // 11. q2 = h @ cross_w[:, :768] + cross_b[:768]  (half out)
    gemm_f16_kernel<<<dim3(768/128, M/128), blk, GEMM_SMEM_BYTES>>>(
        hbuf, 768, wt + OFF_CROSS, 768, cross_b, nullptr, q2, 768, M, 768, 768, 0);
    // 12. ekv = encoder_x @ cross_w[:, 768:] + cross_b[768:]  (2056 x 1536, half)
    gemm_f16_kernel<<<dim3(1536/128, (EROWS + 127)/128), blk, GEMM_SMEM_BYTES>>>(
        enc, 768, wt + OFF_CROSS + 768 * 768, 768, cross_b + 768, nullptr,
        ekv, 1536, EROWS, 1536, 768, 0);
    // 13. cross-attention (non-causal, Tk = 257, V natural from ekv)
    attn_f16_kernel<<<ga, blk, ATTN_SMEM_BYTES>>>(
        q2, 768, ekv, 1536, ekv + 768, 1536, obuf, 768, TLEN, SLEN, 0);
    // 14. x2 = x1 + o2 @ cross_proj_w + cross_proj_b  (float out, in-place resid)
    gemm_f16_kernel<<<dim3(768/128, M/128), blk, GEMM_SMEM_BYTES>>>(
        obuf, 768, wt + OFF_CPROJ, 768, cross_proj_b, xbuf, xbuf, 768, M, 768, 768, 1);
    // 15. h = LN3(x2)
    ln_kernel<<<M, blk>>>(xbuf, ln3_g, ln3_b, hbuf);
    // 16. wconv fc
    wconv_kernel<<<dim3(3072/32, 768/32),  blk>>>(fc_w,         wt + OFF_FC,    768, 3072);
    // 17. fc = GELU(h @ fc_w + fc_b)  (8192 x 3072, half out)
    gemm_f16_kernel<<<dim3(3072/128, M/128), blk, GEMM_SMEM_BYTES>>>(
        hbuf, 768, wt + OFF_FC, 768, fc_b, nullptr, big, 3072, M, 3072, 768, 2);
    // 18. wconv proj
    wconv_kernel<<<dim3(768/32,  3072/32), blk>>>(proj_w,       wt + OFF_PROJ,  3072, 768);
    // 19. out = x2 + fc @ proj_w + proj_b  (float out)
    gemm_f16_kernel<<<dim3(768/128, M/128), blk, GEMM_SMEM_BYTES>>>(
        big, 3072, wt + OFF_PROJ, 3072, proj_b, xbuf, (float*)d_out, 768, M, 768, 3072, 1);
}

// round 15
// speedup vs baseline: 1.2988x; 1.1513x over previous
#include <cuda_runtime.h>
#include <cuda_fp16.h>
#include <math.h>
#include <stddef.h>
#include <stdint.h>

// Problem constants
#define D_MODEL 768
#define NHEAD   12
#define HDIM    64
#define BATCH   8
#define TLEN    1024
#define SLEN    257
#define MROWS   (BATCH * TLEN)   // 8192
#define EROWS   (BATCH * SLEN)   // 2056

// ---------------- scratch (static device globals; no allocation) ------------
__device__ __half g_big[(size_t)MROWS * 3072];
__device__ __half g_h  [(size_t)MROWS * D_MODEL];
__device__ __half g_o  [(size_t)MROWS * D_MODEL];
__device__ float  g_x  [(size_t)MROWS * D_MODEL];
__device__ __half g_q2 [(size_t)MROWS * D_MODEL];
__device__ __half g_ekv[(size_t)EROWS * 1536];
__device__ __half g_enc[(size_t)EROWS * D_MODEL];
__device__ __half g_wt [9437184];   // converted+transposed weights

// WT offsets (halfs)
#define OFF_ATTN   0          // [2304][768]
#define OFF_APROJ  1769472    // [768][768]
#define OFF_CROSS  2359296    // [2304][768]
#define OFF_CPROJ  4128768    // [768][768]
#define OFF_FC     4718592    // [3072][768]
#define OFF_PROJ   7077888    // [768][3072]

// ------------------------------ helpers --------------------------------------
__device__ __forceinline__ float tanh_fast(float x) {
    float y;
    asm("tanh.approx.f32 %0, %1;" : "=f"(y) : "f"(x));
    return y;
}
__device__ __forceinline__ float gelu_tanh(float v) {
    return 0.5f * v * (1.f + tanh_fast(0.7978845608028654f * (v + 0.044715f * v * v * v)));
}

__device__ __forceinline__ void mma_f16(float c[4],
    uint32_t a0, uint32_t a1, uint32_t a2, uint32_t a3,
    uint32_t b0, uint32_t b1)
{
    asm volatile(
        "mma.sync.aligned.m16n8k16.row.col.f32.f16.f16.f32 "
        "{%0,%1,%2,%3}, {%4,%5,%6,%7}, {%8,%9}, {%0,%1,%2,%3};"
        : "+f"(c[0]), "+f"(c[1]), "+f"(c[2]), "+f"(c[3])
        : "r"(a0), "r"(a1), "r"(a2), "r"(a3), "r"(b0), "r"(b1));
}

__device__ __forceinline__ void cp16(uint32_t dst_smem, const void* src) {
    asm volatile("cp.async.cg.shared.global [%0], [%1], 16;"
                 :: "r"(dst_smem), "l"(src));
}

__device__ __forceinline__ void ldsm_x4(
    uint32_t& r0, uint32_t& r1, uint32_t& r2, uint32_t& r3, uint32_t addr)
{
    asm volatile("ldmatrix.sync.aligned.m8n8.x4.shared.b16 {%0,%1,%2,%3}, [%4];"
                 : "=r"(r0), "=r"(r1), "=r"(r2), "=r"(r3) : "r"(addr));
}

__device__ __forceinline__ void ldsm_x4_t(
    uint32_t& r0, uint32_t& r1, uint32_t& r2, uint32_t& r3, uint32_t addr)
{
    asm volatile("ldmatrix.sync.aligned.m8n8.x4.trans.shared.b16 {%0,%1,%2,%3}, [%4];"
                 : "=r"(r0), "=r"(r1), "=r"(r2), "=r"(r3) : "r"(addr));
}

__device__ __forceinline__ uint32_t pack_h2(float a, float b) {
    __half2 h = __floats2half2_rn(a, b);
    return *reinterpret_cast<uint32_t*>(&h);
}

// ---------------------------- LayerNorm (d = 768) ---------------------------
__global__ __launch_bounds__(256) void ln_kernel(
    const float* __restrict__ x, const float* __restrict__ g,
    const float* __restrict__ b, __half* __restrict__ y)
{
    const int row = blockIdx.x;
    const int tid = threadIdx.x;
    const float* xr = x + (size_t)row * D_MODEL;

    float v0 = xr[tid], v1 = xr[tid + 256], v2 = xr[tid + 512];
    float s  = v0 + v1 + v2;
    float sq = v0 * v0 + v1 * v1 + v2 * v2;

    #pragma unroll
    for (int off = 16; off >= 1; off >>= 1) {
        s  += __shfl_xor_sync(0xffffffffu, s,  off);
        sq += __shfl_xor_sync(0xffffffffu, sq, off);
    }
    __shared__ float ss[8], ssq[8];
    int w = tid >> 5, l = tid & 31;
    if (l == 0) { ss[w] = s; ssq[w] = sq; }
    __syncthreads();
    float st = 0.f, sqt = 0.f;
    #pragma unroll
    for (int i = 0; i < 8; i++) { st += ss[i]; sqt += ssq[i]; }

    const float mean = st * (1.f / 768.f);
    const float var  = sqt * (1.f / 768.f) - mean * mean;
    const float rstd = rsqrtf(var + 1e-5f);

    __half* yr = y + (size_t)row * D_MODEL;
    yr[tid]       = __float2half_rn((v0 - mean) * rstd * g[tid]       + b[tid]);
    yr[tid + 256] = __float2half_rn((v1 - mean) * rstd * g[tid + 256] + b[tid + 256]);
    yr[tid + 512] = __float2half_rn((v2 - mean) * rstd * g[tid + 512] + b[tid + 512]);
}

// ------------------- weight convert + transpose (fp32->fp16) -----------------
__global__ __launch_bounds__(256) void wconv_kernel(
    const float* __restrict__ src, __half* __restrict__ dst, int K, int N)
{
    __shared__ float t[32][33];
    const int k0 = blockIdx.y * 32, n0 = blockIdx.x * 32;
    const int tx = threadIdx.x & 31, ty = threadIdx.x >> 5;
    #pragma unroll
    for (int i = 0; i < 32; i += 8)
        t[ty + i][tx] = src[(size_t)(k0 + ty + i) * N + n0 + tx];
    __syncthreads();
    #pragma unroll
    for (int i = 0; i < 32; i += 8)
        dst[(size_t)(n0 + ty + i) * K + k0 + tx] = __float2half_rn(t[tx][ty + i]);
}

// -------------------------- encoder_x fp32 -> fp16 ---------------------------
__global__ __launch_bounds__(256) void f2h_kernel(
    const float* __restrict__ src, __half* __restrict__ dst, int n)
{
    int i = blockIdx.x * 256 + threadIdx.x;
    if (i < n) dst[i] = __float2half_rn(src[i]);
}

// ------------------------------ fp16 GEMM ------------------------------------
// C[M,N] = A[M,K] @ WT^T + bias (+resid | GELU). m16n8k16 fp16, fp32 acc.
// WT is [N][K] half. CTA 128x128xKT64, 256 thr (8 warps 2m x 4n), warp 64x32.
// 3-stage cp.async pipeline (wait_group 1). SMEM rows pitch 128B with XOR
// swizzle: physical 16B-chunk = logical ^ (row & 7). Conflict-free for
// cp.async stores and all ldmatrix phases (row stride = exactly 32 banks).
#define GPITCH 128
#define GSTG   (256 * GPITCH)            // 32768 B per stage (A 128 + B 128 rows)
#define GB_OFF (128 * GPITCH)            // B rows start
#define GEMM_SMEM_BYTES (3 * GSTG)       // 98304

__global__ __launch_bounds__(256, 2) void gemm_f16_kernel(
    const __half* __restrict__ A, int lda,
    const __half* __restrict__ WT, int ldb,
    const float* __restrict__ bias,
    const float* __restrict__ resid,
    void* __restrict__ Cv, int ldc,
    int M, int N, int K, int mode)   // 0: bias->half, 1: bias+resid->float, 2: bias+gelu->half
{
    extern __shared__ char smc[];
    const uint32_t smem0 = (uint32_t)__cvta_generic_to_shared(smc);
    const int tid = threadIdx.x, lane = tid & 31, wid = tid >> 5;
    const int wm = wid & 1, wn = wid >> 1;
    const int g = lane >> 2, tg = lane & 3;
    const int bm = blockIdx.y * 128, bn = blockIdx.x * 128;

    // loaders: 2 threads per row; each does 4 swizzled cp16 (64B) of the 128B row
    const int row = tid >> 1, hsel = tid & 1;
    int ar = bm + row; if (ar >= M) ar = M - 1;
    const __half* aptr = A  + (size_t)ar * lda + hsel * 32;
    const __half* bptr = WT + (size_t)(bn + row) * ldb + hsel * 32;
    const uint32_t dAr = smem0 + row * GPITCH;            // + stage + chunk
    const uint32_t dBr = smem0 + GB_OFF + row * GPITCH;
    uint32_t cj[4];
    #pragma unroll
    for (int j = 0; j < 4; j++)
        cj[j] = (uint32_t)((((hsel << 2) + j) ^ (row & 7)) * 16);

    // ldmatrix bases (swizzle applied per-ks via XOR with rsw)
    const int rsw = lane & 7;
    const uint32_t aRow = smem0 + (wm * 64 + (lane & 15)) * GPITCH;
    const uint32_t bRow = smem0 + GB_OFF
        + (wn * 32 + (lane & 7) + ((lane >> 4) << 3)) * GPITCH;
    const int aCb = lane >> 4;            // chunk base: + 2*ks, then ^ rsw
    const int bCb = (lane >> 3) & 1;

    float acc[4][4][4];
    #pragma unroll
    for (int mt = 0; mt < 4; mt++)
        #pragma unroll
        for (int nt = 0; nt < 4; nt++)
            #pragma unroll
            for (int e = 0; e < 4; e++) acc[mt][nt][e] = 0.f;

    const int nk = K >> 6;   // K/64

    // prologue: stages 0 and 1
    #pragma unroll
    for (int st = 0; st < 2; st++) {
        if (st < nk) {
            const __half* pa = aptr + (size_t)st * 64;
            const __half* pb = bptr + (size_t)st * 64;
            const uint32_t so = st * GSTG;
            #pragma unroll
            for (int j = 0; j < 4; j++) {
                cp16(dAr + so + cj[j], pa + j * 8);
                cp16(dBr + so + cj[j], pb + j * 8);
            }
        }
        asm volatile("cp.async.commit_group;");
    }

    int buf = 0;   // kt % 3
    for (int kt = 0; kt < nk; kt++) {
        asm volatile("cp.async.wait_group 1;");   // stage kt resident
        __syncthreads();

        // issue stage kt+2 into buffer (kt+2)%3 (readers done at iter kt-1)
        if (kt + 2 < nk) {
            const int nb = (buf + 2 >= 3) ? buf - 1 : buf + 2;
            const __half* pa = aptr + (size_t)(kt + 2) * 64;
            const __half* pb = bptr + (size_t)(kt + 2) * 64;
            const uint32_t so = nb * GSTG;
            #pragma unroll
            for (int j = 0; j < 4; j++) {
                cp16(dAr + so + cj[j], pa + j * 8);
                cp16(dBr + so + cj[j], pb + j * 8);
            }
        }
        asm volatile("cp.async.commit_group;");

        const uint32_t so = buf * GSTG;

        #pragma unroll
        for (int ks = 0; ks < 4; ks++) {
            const uint32_t ca = (uint32_t)(((aCb + 2 * ks) ^ rsw) * 16);
            const uint32_t cb = (uint32_t)(((bCb + 2 * ks) ^ rsw) * 16);
            uint32_t af[4][4], bf[4][2];
            #pragma unroll
            for (int mt = 0; mt < 4; mt++)
                ldsm_x4(af[mt][0], af[mt][1], af[mt][2], af[mt][3],
                        aRow + so + mt * (16 * GPITCH) + ca);
            #pragma unroll
            for (int p = 0; p < 2; p++) {
                uint32_t r0, r1, r2, r3;
                ldsm_x4(r0, r1, r2, r3, bRow + so + p * (16 * GPITCH) + cb);
                bf[2 * p][0] = r0;     bf[2 * p][1] = r1;
                bf[2 * p + 1][0] = r2; bf[2 * p + 1][1] = r3;
            }
            #pragma unroll
            for (int mt = 0; mt < 4; mt++)
                #pragma unroll
                for (int nt = 0; nt < 4; nt++)
                    mma_f16(acc[mt][nt], af[mt][0], af[mt][1], af[mt][2], af[mt][3],
                            bf[nt][0], bf[nt][1]);
        }
        buf = (buf + 1 >= 3) ? 0 : buf + 1;
    }

    // ---- epilogue ----
    #pragma unroll
    for (int mt = 0; mt < 4; mt++) {
        const int r0 = bm + wm * 64 + mt * 16 + g;
        #pragma unroll
        for (int h2 = 0; h2 < 2; h2++) {
            const int rr = r0 + 8 * h2;
            if (rr >= M) continue;
            #pragma unroll
            for (int nt = 0; nt < 4; nt++) {
                const int col = bn + wn * 32 + nt * 8 + 2 * tg;
                float ox = acc[mt][nt][2 * h2];
                float oy = acc[mt][nt][2 * h2 + 1];
                float2 bv = *(const float2*)&bias[col];
                ox += bv.x; oy += bv.y;
                if (mode == 1) {
                    float2 rv = *(const float2*)&resid[(size_t)rr * ldc + col];
                    ox += rv.x; oy += rv.y;
                    *(float2*)&((float*)Cv)[(size_t)rr * ldc + col] = make_float2(ox, oy);
                } else {
                    if (mode == 2) { ox = gelu_tanh(ox); oy = gelu_tanh(oy); }
                    __half2 hv = __floats2half2_rn(ox, oy);
                    *(__half2*)&((__half*)Cv)[(size_t)rr * ldc + col] = hv;
                }
            }
        }
    }
}

// ------------------- fp16 tensor-core flash attention -------------------------
// CTA: 128 q-rows x 64-key tiles, 256 thr = 8 warps; K/V double-buffered.
// V consumed in NATURAL [t][d] layout via ldmatrix.trans (no pre-transpose).
#define APITCH 144
#define AQ_OFF  0
#define AKSTG   (64 * APITCH)
#define AK_OFF  (128 * APITCH)
#define AV_OFF  (AK_OFF + 2 * AKSTG)
#define AP_OFF  (AV_OFF + 2 * AKSTG)
#define ATTN_SMEM_BYTES (AP_OFF + 128 * APITCH)     // 73728

__global__ __launch_bounds__(256, 2) void attn_f16_kernel(
    const __half* __restrict__ Qp, int q_rs,
    const __half* __restrict__ Kp, int k_rs,
    const __half* __restrict__ Vp, int v_rs,    // natural [t][d] rows
    __half* __restrict__ Op, int o_rs,
    int Tq, int Tk, int causal)
{
    extern __shared__ char smc[];
    const uint32_t smem0 = (uint32_t)__cvta_generic_to_shared(smc);
    uint32_t* P32 = (uint32_t*)(smc + AP_OFF);

    const int tid = threadIdx.x, lane = tid & 31, wid = tid >> 5;
    const int g = lane >> 2, tg = lane & 3;
    const int b = blockIdx.z, h = blockIdx.y;
    const int q0 = blockIdx.x * 128;
    const int rw = wid * 16;

    const __half* qbase = Qp + (size_t)b * Tq * q_rs + h * HDIM;
    const __half* kbase = Kp + (size_t)b * Tk * k_rs + h * HDIM;
    const __half* vbase = Vp + (size_t)b * Tk * v_rs + h * HDIM;

    const uint32_t lmRow16 = (lane & 15) * APITCH + (lane >> 4) * 16;
    const uint32_t lmRowB  = ((lane & 7) + ((lane >> 4) << 3)) * APITCH
                           + ((lane >> 3) & 1) * 16;
    const uint32_t lmRowVT = ((lane & 7) + ((lane >> 3) & 1) * 8) * APITCH
                           + (lane >> 4) * 16;
    const uint32_t qLm = smem0 + AQ_OFF + rw * APITCH + lmRow16;
    const uint32_t kLm = smem0 + AK_OFF + lmRowB;
    const uint32_t vLm = smem0 + AV_OFF + lmRowVT;
    const uint32_t pLm = smem0 + AP_OFF + rw * APITCH + lmRow16;

    const int kv_r = tid >> 2;
    const int kv_c = (tid & 3) * 16;
    const uint32_t dkBase = smem0 + AK_OFF + kv_r * APITCH + (tid & 3) * 32;
    const uint32_t dvBase = smem0 + AV_OFF + kv_r * APITCH + (tid & 3) * 32;

    const int ntiles = causal ? 2 * (blockIdx.x + 1) : ((Tk + 63) >> 6);

    {
        const int r = tid >> 1, hs = tid & 1;
        const __half* src = qbase + (size_t)(q0 + r) * q_rs + hs * 32;
        const uint32_t dst = smem0 + AQ_OFF + r * APITCH + hs * 64;
        #pragma unroll
        for (int j = 0; j < 4; j++) cp16(dst + j * 16, src + j * 8);
        asm volatile("cp.async.commit_group;");
    }
    {
        int sr = kv_r; if (sr >= Tk) sr = Tk - 1;
        const __half* ks = kbase + (size_t)sr * k_rs + kv_c;
        const __half* vs = vbase + (size_t)sr * v_rs + kv_c;
        cp16(dkBase, ks);      cp16(dkBase + 16, ks + 8);
        cp16(dvBase, vs);      cp16(dvBase + 16, vs + 8);
        asm volatile("cp.async.commit_group;");
    }

    float mrun[2] = {-1e30f, -1e30f}, lrun[2] = {0.f, 0.f};
    float o[8][4];
    #pragma unroll
    for (int nf = 0; nf < 8; nf++)
        #pragma unroll
        for (int e = 0; e < 4; e++) o[nf][e] = 0.f;

    for (int kt = 0; kt < ntiles; kt++) {
        const int k0 = kt * 64;
        asm volatile("cp.async.wait_group 0;");
        __syncthreads();

        if (kt + 1 < ntiles) {
            const int k0n = k0 + 64;
            int sr = k0n + kv_r; if (sr >= Tk) sr = Tk - 1;
            const __half* ks = kbase + (size_t)sr * k_rs + kv_c;
            const __half* vs = vbase + (size_t)sr * v_rs + kv_c;
            const uint32_t bo = ((kt + 1) & 1) * AKSTG;
            cp16(dkBase + bo, ks);      cp16(dkBase + bo + 16, ks + 8);
            cp16(dvBase + bo, vs);      cp16(dvBase + bo + 16, vs + 8);
            asm volatile("cp.async.commit_group;");
        }

        const uint32_t bo = (kt & 1) * AKSTG;

        float sc[8][4];
        #pragma unroll
        for (int nf = 0; nf < 8; nf++)
            #pragma unroll
            for (int e = 0; e < 4; e++) sc[nf][e] = 0.f;

        #pragma unroll
        for (int ks = 0; ks < 4; ks++) {
            uint32_t a0, a1, a2, a3;
            ldsm_x4(a0, a1, a2, a3, qLm + ks * 32);
            #pragma unroll
            for (int p = 0; p < 4; p++) {
                uint32_t b00, b01, b10, b11;
                ldsm_x4(b00, b01, b10, b11, kLm + bo + p * (16 * APITCH) + ks * 32);
                mma_f16(sc[2 * p],     a0, a1, a2, a3, b00, b01);
                mma_f16(sc[2 * p + 1], a0, a1, a2, a3, b10, b11);
            }
        }

        const int qi0 = q0 + rw + g, qi1 = qi0 + 8;
        const int cmax0 = causal ? min(qi0, Tk - 1) : (Tk - 1);
        const int cmax1 = causal ? min(qi1, Tk - 1) : (Tk - 1);
        float m0 = -1e30f, m1 = -1e30f;
        #pragma unroll
        for (int nf = 0; nf < 8; nf++) {
            const int c0i = k0 + 8 * nf + 2 * tg;
            const int c1i = c0i + 1;
            sc[nf][0] = (c0i <= cmax0) ? sc[nf][0] * 0.125f : -1e30f;
            sc[nf][1] = (c1i <= cmax0) ? sc[nf][1] * 0.125f : -1e30f;
            sc[nf][2] = (c0i <= cmax1) ? sc[nf][2] * 0.125f : -1e30f;
            sc[nf][3] = (c1i <= cmax1) ? sc[nf][3] * 0.125f : -1e30f;
            m0 = fmaxf(m0, fmaxf(sc[nf][0], sc[nf][1]));
            m1 = fmaxf(m1, fmaxf(sc[nf][2], sc[nf][3]));
        }
        #pragma unroll
        for (int off = 1; off < 4; off <<= 1) {
            m0 = fmaxf(m0, __shfl_xor_sync(0xffffffffu, m0, off));
            m1 = fmaxf(m1, __shfl_xor_sync(0xffffffffu, m1, off));
        }
        const float mn0 = fmaxf(mrun[0], m0), mn1 = fmaxf(mrun[1], m1);
        const float corr0 = __expf(mrun[0] - mn0), corr1 = __expf(mrun[1] - mn1);
        mrun[0] = mn0; mrun[1] = mn1;

        float s0 = 0.f, s1 = 0.f;
        #pragma unroll
        for (int nf = 0; nf < 8; nf++) {
            float p00 = __expf(sc[nf][0] - mn0);
            float p01 = __expf(sc[nf][1] - mn0);
            float p10 = __expf(sc[nf][2] - mn1);
            float p11 = __expf(sc[nf][3] - mn1);
            s0 += p00 + p01; s1 += p10 + p11;
            P32[(rw + g)     * 36 + 4 * nf + tg] = pack_h2(p00, p01);
            P32[(rw + g + 8) * 36 + 4 * nf + tg] = pack_h2(p10, p11);
            o[nf][0] *= corr0; o[nf][1] *= corr0;
            o[nf][2] *= corr1; o[nf][3] *= corr1;
        }
        #pragma unroll
        for (int off = 1; off < 4; off <<= 1) {
            s0 += __shfl_xor_sync(0xffffffffu, s0, off);
            s1 += __shfl_xor_sync(0xffffffffu, s1, off);
        }
        lrun[0] = lrun[0] * corr0 + s0;
        lrun[1] = lrun[1] * corr1 + s1;
        __syncwarp();

        #pragma unroll
        for (int ks = 0; ks < 4; ks++) {
            uint32_t a0, a1, a2, a3;
            ldsm_x4(a0, a1, a2, a3, pLm + ks * 32);
            #pragma unroll
            for (int p = 0; p < 4; p++) {
                uint32_t b00, b01, b10, b11;
                ldsm_x4_t(b00, b01, b10, b11,
                          vLm + bo + ks * (16 * APITCH) + p * 32);
                mma_f16(o[2 * p],     a0, a1, a2, a3, b00, b01);
                mma_f16(o[2 * p + 1], a0, a1, a2, a3, b10, b11);
            }
        }
    }

    const float inv0 = 1.f / lrun[0], inv1 = 1.f / lrun[1];
    const int t0 = q0 + rw + g, t1 = t0 + 8;
    __half* out0 = Op + ((size_t)b * Tq + t0) * o_rs + h * HDIM;
    __half* out1 = Op + ((size_t)b * Tq + t1) * o_rs + h * HDIM;
    #pragma unroll
    for (int nf = 0; nf < 8; nf++) {
        const int col = 8 * nf + 2 * tg;
        *(__half2*)&out0[col] = __floats2half2_rn(o[nf][0] * inv0, o[nf][1] * inv0);
        *(__half2*)&out1[col] = __floats2half2_rn(o[nf][2] * inv1, o[nf][3] * inv1);
    }
}

// ------------------------------- launch --------------------------------------
extern "C" void kernel_launch(void* const* d_in, const int* in_sizes, int n_in,
                              void* d_out, int out_size)
{
    const float* x            = (const float*)d_in[0];
    const float* encoder_x    = (const float*)d_in[1];
    const float* ln1_g        = (const float*)d_in[2];
    const float* ln1_b        = (const float*)d_in[3];
    const float* ln2_g        = (const float*)d_in[4];
    const float* ln2_b        = (const float*)d_in[5];
    const float* ln3_g        = (const float*)d_in[6];
    const float* ln3_b        = (const float*)d_in[7];
    const float* attn_w       = (const float*)d_in[8];
    const float* attn_b       = (const float*)d_in[9];
    const float* attn_proj_w  = (const float*)d_in[10];
    const float* attn_proj_b  = (const float*)d_in[11];
    const float* cross_w      = (const float*)d_in[12];
    const float* cross_b      = (const float*)d_in[13];
    const float* cross_proj_w = (const float*)d_in[14];
    const float* cross_proj_b = (const float*)d_in[15];
    const float* fc_w         = (const float*)d_in[16];
    const float* fc_b         = (const float*)d_in[17];
    const float* proj_w       = (const float*)d_in[18];
    const float* proj_b       = (const float*)d_in[19];

    __half *big, *hbuf, *obuf, *q2, *ekv, *enc, *wt;
    float  *xbuf;
    cudaGetSymbolAddress((void**)&big,  g_big);
    cudaGetSymbolAddress((void**)&hbuf, g_h);
    cudaGetSymbolAddress((void**)&obuf, g_o);
    cudaGetSymbolAddress((void**)&xbuf, g_x);
    cudaGetSymbolAddress((void**)&q2,   g_q2);
    cudaGetSymbolAddress((void**)&ekv,  g_ekv);
    cudaGetSymbolAddress((void**)&enc,  g_enc);
    cudaGetSymbolAddress((void**)&wt,   g_wt);

    cudaFuncSetAttribute(attn_f16_kernel,
                         cudaFuncAttributeMaxDynamicSharedMemorySize,
                         ATTN_SMEM_BYTES);
    cudaFuncSetAttribute(gemm_f16_kernel,
                         cudaFuncAttributeMaxDynamicSharedMemorySize,
                         GEMM_SMEM_BYTES);

    const int M = MROWS;        // 8192
    dim3 blk(256);
    dim3 ga(TLEN / 128, NHEAD, BATCH);   // 8 x 12 x 8

    // 1. wconv attn
    wconv_kernel<<<dim3(2304/32, 768/32),  blk>>>(attn_w,       wt + OFF_ATTN,  768, 2304);
    // 2. wconv attn_proj
    wconv_kernel<<<dim3(768/32,  768/32),  blk>>>(attn_proj_w,  wt + OFF_APROJ, 768, 768);
    // 3. encoder_x -> half
    f2h_kernel<<<(EROWS * D_MODEL + 255) / 256, blk>>>(encoder_x, enc, EROWS * D_MODEL);
    // 4. h = LN1(x)
    ln_kernel<<<M, blk>>>(x, ln1_g, ln1_b, hbuf);
    // 5. wconv cross
    wconv_kernel<<<dim3(2304/32, 768/32),  blk>>>(cross_w,      wt + OFF_CROSS, 768, 2304);
    // 6. qkv = h @ attn_w + attn_b  (8192 x 2304, half out)
    gemm_f16_kernel<<<dim3(2304/128, M/128), blk, GEMM_SMEM_BYTES>>>(
        hbuf, 768, wt + OFF_ATTN, 768, attn_b, nullptr, big, 2304, M, 2304, 768, 0);
    // 7. causal self-attention (V natural from qkv)
    attn_f16_kernel<<<ga, blk, ATTN_SMEM_BYTES>>>(
        big, 2304, big + 768, 2304, big + 1536, 2304, obuf, 768, TLEN, TLEN, 1);
    // 8. x1 = x + o @ attn_proj_w + attn_proj_b  (float out)
    gemm_f16_kernel<<<dim3(768/128, M/128), blk, GEMM_SMEM_BYTES>>>(
        obuf, 768, wt + OFF_APROJ, 768, attn_proj_b, x, xbuf, 768, M, 768, 768, 1);
    // 9. h = LN2(x1)
    ln_kernel<<<M, blk>>>(xbuf, ln2_g, ln2_b, hbuf);
    // 10. wconv cross_proj
    wconv_kernel<<<dim3(768/32,  768/32),  blk>>>(cross_proj_w, wt + OFF_CPROJ, 768, 768);
    // 11. q2 = h @ cross_w[:, :768] + cross_b[:768]  (half out)
    gemm_f16_kernel<<<dim3(768/128, M/128), blk, GEMM_SMEM_BYTES>>>(
        hbuf, 768, wt + OFF_CROSS, 768, cross_b, nullptr, q2, 768, M, 768, 768, 0);
    // 12. ekv = encoder_x @ cross_w[:, 768:] + cross_b[768:]  (2056 x 1536, half)
    gemm_f16_kernel<<<dim3(1536/128, (EROWS + 127)/128), blk, GEMM_SMEM_BYTES>>>(
        enc, 768, wt + OFF_CROSS + 768 * 768, 768, cross_b + 768, nullptr,
        ekv, 1536, EROWS, 1536, 768, 0);
    // 13. cross-attention (non-causal, Tk = 257, V natural from ekv)
    attn_f16_kernel<<<ga, blk, ATTN_SMEM_BYTES>>>(
        q2, 768, ekv, 1536, ekv + 768, 1536, obuf, 768, TLEN, SLEN, 0);
    // 14. x2 = x1 + o2 @ cross_proj_w + cross_proj_b  (float out, in-place resid)
    gemm_f16_kernel<<<dim3(768/128, M/128), blk, GEMM_SMEM_BYTES>>>(
        obuf, 768, wt + OFF_CPROJ, 768, cross_proj_b, xbuf, xbuf, 768, M, 768, 768, 1);
    // 15. h = LN3(x2)
    ln_kernel<<<M, blk>>>(xbuf, ln3_g, ln3_b, hbuf);
    // 16. wconv fc
    wconv_kernel<<<dim3(3072/32, 768/32),  blk>>>(fc_w,         wt + OFF_FC,    768, 3072);
    // 17. fc = GELU(h @ fc_w + fc_b)  (8192 x 3072, half out)
    gemm_f16_kernel<<<dim3(3072/128, M/128), blk, GEMM_SMEM_BYTES>>>(
        hbuf, 768, wt + OFF_FC, 768, fc_b, nullptr, big, 3072, M, 3072, 768, 2);
    // 18. wconv proj
    wconv_kernel<<<dim3(768/32,  3072/32), blk>>>(proj_w,       wt + OFF_PROJ,  3072, 768);
    // 19. out = x2 + fc @ proj_w + proj_b  (float out)
    gemm_f16_kernel<<<dim3(768/128, M/128), blk, GEMM_SMEM_BYTES>>>(
        big, 3072, wt + OFF_PROJ, 3072, proj_b, xbuf, (float*)d_out, 768, M, 768, 3072, 1);
}